// round 1
// baseline (speedup 1.0000x reference)
#include <cuda_runtime.h>
#include <cstdint>

#define CC   128
#define KK   32
#define HH   8
#define DHH  16
#define BB   4
#define GG   128
#define MAXN 100352

// ---------------- device scratch (static, allowed) ----------------
__device__ int   g_grid[BB*GG*GG*GG];      // 32 MB voxel hash
__device__ float g_x  [MAXN*CC];           // conv out -> BN/ReLU (in place)
__device__ float g_q  [MAXN*CC];
__device__ float g_o  [MAXN*CC];
__device__ float g_ao [MAXN*CC];
__device__ float g_sum[CC];
__device__ float g_sumsq[CC];
__device__ float g_bkmax[BB*KK];
__device__ float g_bksum[BB*KK];
__device__ float g_ctx[BB*KK*CC];
__device__ float g_khv[2*BB*KK*CC];        // kh then vh, [bk][c]
__device__ float g_wsum[CC*CC];            // bottleneck_w[:, :C] + [:, C:]

// ---------------- init: grid=-1, zero accumulators, build Wsum ----------------
__global__ void k_init(const float* __restrict__ bw) {
    int i = blockIdx.x * blockDim.x + threadIdx.x;
    const int tot = BB*GG*GG*GG;
    for (int idx = i; idx < tot; idx += gridDim.x * blockDim.x) g_grid[idx] = -1;
    if (i < BB*KK*CC) g_ctx[i] = 0.f;
    if (i < CC*CC) {
        int c = i >> 7, j = i & 127;
        g_wsum[i] = bw[c*2*CC + j] + bw[c*2*CC + CC + j];
    }
    if (i < CC) { g_sum[i] = 0.f; g_sumsq[i] = 0.f; }
}

__global__ void k_scatter(const int* __restrict__ coords, int N) {
    int i = blockIdx.x * blockDim.x + threadIdx.x;
    if (i >= N) return;
    int b = coords[4*i], x = coords[4*i+1], y = coords[4*i+2], z = coords[4*i+3];
    g_grid[((b*GG + x)*GG + y)*GG + z] = i;
}

// ---------------- submanifold 3x3x3 conv: 64 pts x 128 out per CTA ----------------
__global__ void __launch_bounds__(256) k_conv(const float* __restrict__ feats,
                                              const float* __restrict__ Wc,
                                              const int*   __restrict__ coords,
                                              int N) {
    __shared__ int   nbr[27][64];
    __shared__ float As[16][64];
    __shared__ float Ws[16][CC];
    const int t  = threadIdx.x;
    const int n0 = blockIdx.x * 64;

    for (int e = t; e < 27*64; e += 256) {
        int k = e / 64, m = e % 64;
        int n = n0 + m, j = -1;
        if (n < N) {
            int b = coords[4*n];
            int x = coords[4*n+1] + k/9 - 1;
            int y = coords[4*n+2] + (k/3)%3 - 1;
            int z = coords[4*n+3] + k%3 - 1;
            if ((unsigned)x < GG && (unsigned)y < GG && (unsigned)z < GG)
                j = g_grid[((b*GG + x)*GG + y)*GG + z];
        }
        nbr[k][m] = j;
    }
    __syncthreads();

    float acc[4][8];
    #pragma unroll
    for (int q = 0; q < 4; q++)
        #pragma unroll
        for (int r = 0; r < 8; r++) acc[q][r] = 0.f;

    const int mi  = t & 15, ci = t >> 4;      // compute mapping
    const int lm  = t >> 2, ljj = (t & 3) * 4; // A-load mapping
    const int lj  = t >> 4, lc  = (t & 15) * 8; // W-load mapping

    for (int k = 0; k < 27; k++) {
        const float* wb = Wc + k * CC * CC;
        const int idxm = nbr[k][lm];
        for (int js = 0; js < 8; js++) {
            const int j0 = js * 16;
            float4 v = make_float4(0.f, 0.f, 0.f, 0.f);
            if (idxm >= 0) v = *(const float4*)(feats + (size_t)idxm*CC + j0 + ljj);
            As[ljj+0][lm] = v.x; As[ljj+1][lm] = v.y;
            As[ljj+2][lm] = v.z; As[ljj+3][lm] = v.w;
            float4 w0 = *(const float4*)(wb + (j0 + lj)*CC + lc);
            float4 w1 = *(const float4*)(wb + (j0 + lj)*CC + lc + 4);
            *(float4*)&Ws[lj][lc]   = w0;
            *(float4*)&Ws[lj][lc+4] = w1;
            __syncthreads();
            #pragma unroll
            for (int jp = 0; jp < 16; jp++) {
                float4 a  = *(const float4*)&As[jp][mi*4];
                float4 b0 = *(const float4*)&Ws[jp][ci*8];
                float4 b1 = *(const float4*)&Ws[jp][ci*8 + 4];
                float av[4] = {a.x, a.y, a.z, a.w};
                float wv[8] = {b0.x, b0.y, b0.z, b0.w, b1.x, b1.y, b1.z, b1.w};
                #pragma unroll
                for (int q = 0; q < 4; q++)
                    #pragma unroll
                    for (int r = 0; r < 8; r++) acc[q][r] += av[q] * wv[r];
            }
            __syncthreads();
        }
    }
    #pragma unroll
    for (int q = 0; q < 4; q++) {
        int n = n0 + mi*4 + q;
        if (n < N) {
            float4 o0 = make_float4(acc[q][0], acc[q][1], acc[q][2], acc[q][3]);
            float4 o1 = make_float4(acc[q][4], acc[q][5], acc[q][6], acc[q][7]);
            *(float4*)(g_x + (size_t)n*CC + ci*8)     = o0;
            *(float4*)(g_x + (size_t)n*CC + ci*8 + 4) = o1;
        }
    }
}

// ---------------- BN stats + apply ----------------
__global__ void k_bnstats(int N) {
    const int c  = threadIdx.x;        // 128 threads
    const int n0 = blockIdx.x * 256;
    float s = 0.f, s2 = 0.f;
    for (int p = 0; p < 256; p++) {
        int n = n0 + p;
        if (n >= N) break;
        float v = g_x[(size_t)n*CC + c];
        s += v; s2 += v * v;
    }
    atomicAdd(&g_sum[c], s);
    atomicAdd(&g_sumsq[c], s2);
}

__global__ void k_bnapply(const float* __restrict__ gamma,
                          const float* __restrict__ beta, int N) {
    __shared__ float scl[CC], sft[CC];
    int t = threadIdx.x;
    if (t < CC) {
        float inv = 1.f / (float)N;
        float mu  = g_sum[t] * inv;
        float var = g_sumsq[t] * inv - mu * mu;
        float a   = gamma[t] * rsqrtf(var + 1e-5f);
        scl[t] = a; sft[t] = beta[t] - mu * a;
    }
    __syncthreads();
    const int tot = N * CC;
    for (int i = blockIdx.x * blockDim.x + t; i < tot; i += gridDim.x * blockDim.x) {
        float v = g_x[i] * scl[i & 127] + sft[i & 127];
        g_x[i] = v > 0.f ? v : 0.f;
    }
}

// ---------------- per-(b,k) softmax-over-n stats ----------------
__global__ void k_bk(const float* __restrict__ probs, const int* __restrict__ coords, int N) {
    const int b = blockIdx.x >> 5, k = blockIdx.x & 31;
    __shared__ float red[256];
    const int t = threadIdx.x;
    float lm = -3.4e38f;
    for (int n = t; n < N; n += 256)
        if (coords[4*n] == b) lm = fmaxf(lm, probs[n*KK + k]);
    red[t] = lm; __syncthreads();
    for (int s = 128; s > 0; s >>= 1) { if (t < s) red[t] = fmaxf(red[t], red[t+s]); __syncthreads(); }
    float m = red[0]; __syncthreads();
    float ls = 0.f;
    for (int n = t; n < N; n += 256)
        if (coords[4*n] == b) ls += __expf(probs[n*KK + k] - m);
    red[t] = ls; __syncthreads();
    for (int s = 128; s > 0; s >>= 1) { if (t < s) red[t] += red[t+s]; __syncthreads(); }
    if (t == 0) { g_bkmax[blockIdx.x] = m; g_bksum[blockIdx.x] = red[0]; }
}

// ---------------- ctx[b,k,c] = sum_n w[b,n,k] * x[n,c] ----------------
__global__ void __launch_bounds__(256) k_ctx(const float* __restrict__ probs,
                                             const int* __restrict__ coords, int N) {
    const int b = blockIdx.y;
    const int base0 = blockIdx.x * 512;
    __shared__ float sm[KK], sinv[KK];
    __shared__ float ws[8][KK];
    __shared__ float xs[8][CC];
    const int t = threadIdx.x;
    if (t < KK) { sm[t] = g_bkmax[b*KK + t]; sinv[t] = 1.f / g_bksum[b*KK + t]; }
    float acc[16];
    #pragma unroll
    for (int i = 0; i < 16; i++) acc[i] = 0.f;
    const int k = t >> 3, cg = t & 7;
    bool did = false;
    __syncthreads();
    for (int g = 0; g < 64; g++) {
        int nb = base0 + g * 8;
        if (nb >= N) break;
        int nchk = nb + (t & 7);
        int match = (nchk < N) && (coords[4*nchk] == b);
        if (!__syncthreads_or(match)) continue;
        did = true;
        {   // weights tile
            int p = t >> 5, k2 = t & 31, nn = nb + p;
            int mt = (nn < N) && (coords[4*nn] == b);
            ws[p][k2] = mt ? __expf(probs[nn*KK + k2] - sm[k2]) * sinv[k2] : 0.f;
        }
        {   // feature tile
            int p = t >> 5, c4 = (t & 31) * 4, nn = nb + p;
            float4 v = make_float4(0.f, 0.f, 0.f, 0.f);
            if (nn < N) v = *(const float4*)(g_x + (size_t)nn*CC + c4);
            *(float4*)&xs[p][c4] = v;
        }
        __syncthreads();
        #pragma unroll
        for (int p = 0; p < 8; p++) {
            float w = ws[p][k];
            #pragma unroll
            for (int i = 0; i < 16; i++) acc[i] += w * xs[p][cg + 8*i];
        }
        __syncthreads();
    }
    if (did) {
        #pragma unroll
        for (int i = 0; i < 16; i++)
            atomicAdd(&g_ctx[(b*KK + k)*CC + cg + 8*i], acc[i]);
    }
}

// ---------------- kh/vh = ctx @ Wk.T/Wv.T + bias ----------------
__global__ void k_khv(const float* __restrict__ ipw, const float* __restrict__ ipb) {
    __shared__ float row[CC];
    const int bk = blockIdx.x, t = threadIdx.x;
    if (t < CC) row[t] = g_ctx[bk*CC + t];
    __syncthreads();
    const int c = t & 127, which = t >> 7;            // 0 = kh, 1 = vh
    const float* wr = ipw + (size_t)(CC + which*CC + c) * CC;
    float s = ipb[CC + which*CC + c];
    #pragma unroll 8
    for (int j = 0; j < CC; j++) s += row[j] * wr[j];
    g_khv[which*BB*KK*CC + bk*CC + c] = s;
}

// ---------------- generic 64x128 SGEMM: out = (A @ W.T + bias) * scale ----------------
template<bool HASB>
__global__ void __launch_bounds__(256) k_gemm(const float* __restrict__ A,
                                              const float* __restrict__ W,
                                              const float* __restrict__ bias,
                                              float* __restrict__ out,
                                              int N, float scale) {
    __shared__ float As[16][64];
    __shared__ float Ws[16][CC];
    const int t  = threadIdx.x;
    const int n0 = blockIdx.x * 64;
    float acc[4][8];
    #pragma unroll
    for (int q = 0; q < 4; q++)
        #pragma unroll
        for (int r = 0; r < 8; r++) acc[q][r] = 0.f;
    const int mi = t & 15, ci = t >> 4;
    const int lm = t >> 2, ljj = (t & 3) * 4;
    const int wc = t & 127, wj = (t >> 7) * 8;
    for (int js = 0; js < 8; js++) {
        const int j0 = js * 16;
        {   int n = n0 + lm;
            float4 v = make_float4(0.f, 0.f, 0.f, 0.f);
            if (n < N) v = *(const float4*)(A + (size_t)n*CC + j0 + ljj);
            As[ljj+0][lm] = v.x; As[ljj+1][lm] = v.y;
            As[ljj+2][lm] = v.z; As[ljj+3][lm] = v.w;
        }
        {   float4 w0 = *(const float4*)(W + (size_t)wc*CC + j0 + wj);
            float4 w1 = *(const float4*)(W + (size_t)wc*CC + j0 + wj + 4);
            Ws[wj+0][wc] = w0.x; Ws[wj+1][wc] = w0.y; Ws[wj+2][wc] = w0.z; Ws[wj+3][wc] = w0.w;
            Ws[wj+4][wc] = w1.x; Ws[wj+5][wc] = w1.y; Ws[wj+6][wc] = w1.z; Ws[wj+7][wc] = w1.w;
        }
        __syncthreads();
        #pragma unroll
        for (int jp = 0; jp < 16; jp++) {
            float4 a  = *(const float4*)&As[jp][mi*4];
            float4 b0 = *(const float4*)&Ws[jp][ci*8];
            float4 b1 = *(const float4*)&Ws[jp][ci*8 + 4];
            float av[4] = {a.x, a.y, a.z, a.w};
            float wv[8] = {b0.x, b0.y, b0.z, b0.w, b1.x, b1.y, b1.z, b1.w};
            #pragma unroll
            for (int q = 0; q < 4; q++)
                #pragma unroll
                for (int r = 0; r < 8; r++) acc[q][r] += av[q] * wv[r];
        }
        __syncthreads();
    }
    const int c0 = ci * 8;
    #pragma unroll
    for (int q = 0; q < 4; q++) {
        int n = n0 + mi*4 + q;
        if (n < N) {
            float v[8];
            #pragma unroll
            for (int r = 0; r < 8; r++) {
                float bv = HASB ? bias[c0 + r] : 0.f;
                v[r] = (acc[q][r] + bv) * scale;
            }
            *(float4*)(out + (size_t)n*CC + c0)     = make_float4(v[0], v[1], v[2], v[3]);
            *(float4*)(out + (size_t)n*CC + c0 + 4) = make_float4(v[4], v[5], v[6], v[7]);
        }
    }
}

// ---------------- per-(point, head) attention ----------------
__global__ void __launch_bounds__(512) k_attn(const int* __restrict__ coords, int N) {
    extern __shared__ float smem[];
    float* khs = smem;                 // [bk][d][h]  (4096 floats * 4 batches)
    float* vhs = smem + BB*KK*CC;
    const int t = threadIdx.x;
    for (int e = t; e < BB*KK*CC; e += 512) {
        int bk = e >> 7, r = e & 127, d = r >> 3, h = r & 7;
        int src = bk*CC + h*DHH + d;
        khs[e] = g_khv[src];
        vhs[e] = g_khv[BB*KK*CC + src];
    }
    __syncthreads();
    const int p = t >> 3, h = t & 7;
    const int n = blockIdx.x * 64 + p;
    if (n >= N) return;
    const int b = coords[4*n];
    float qr[16];
    #pragma unroll
    for (int u = 0; u < 4; u++)
        *(float4*)&qr[u*4] = *(const float4*)(g_q + (size_t)n*CC + h*DHH + u*4);
    float sc[KK];
    #pragma unroll
    for (int k = 0; k < KK; k++) {
        const float* kb = khs + ((b*KK + k)*DHH)*HH + h;
        float s = 0.f;
        #pragma unroll
        for (int d = 0; d < DHH; d++) s += qr[d] * kb[d*HH];
        sc[k] = s;
    }
    float m = sc[0];
    #pragma unroll
    for (int k = 1; k < KK; k++) m = fmaxf(m, sc[k]);
    float den = 0.f;
    #pragma unroll
    for (int k = 0; k < KK; k++) { sc[k] = __expf(sc[k] - m); den += sc[k]; }
    const float inv = 1.f / den;
    float od[16];
    #pragma unroll
    for (int d = 0; d < DHH; d++) od[d] = 0.f;
    #pragma unroll
    for (int k = 0; k < KK; k++) {
        float a = sc[k] * inv;
        const float* vb = vhs + ((b*KK + k)*DHH)*HH + h;
        #pragma unroll
        for (int d = 0; d < DHH; d++) od[d] += a * vb[d*HH];
    }
    #pragma unroll
    for (int u = 0; u < 4; u++)
        *(float4*)(g_o + (size_t)n*CC + h*DHH + u*4) = make_float4(od[u*4], od[u*4+1], od[u*4+2], od[u*4+3]);
}

// ---------------- launcher ----------------
extern "C" void kernel_launch(void* const* d_in, const int* in_sizes, int n_in,
                              void* d_out, int out_size) {
    const float* feats  = (const float*)d_in[0];
    const float* probs  = (const float*)d_in[1];
    const float* conv_w = (const float*)d_in[2];
    const float* gamma  = (const float*)d_in[3];
    const float* beta   = (const float*)d_in[4];
    const float* ipw    = (const float*)d_in[5];
    const float* ipb    = (const float*)d_in[6];
    const float* opw    = (const float*)d_in[7];
    const float* opb    = (const float*)d_in[8];
    const float* bw     = (const float*)d_in[9];
    const int*   coords = (const int*)d_in[10];
    float* y = (float*)d_out;
    int N = in_sizes[0] / CC;
    if (N > MAXN) N = MAXN;

    float *px, *pq, *po, *pao, *pws;
    cudaGetSymbolAddress((void**)&px,  g_x);
    cudaGetSymbolAddress((void**)&pq,  g_q);
    cudaGetSymbolAddress((void**)&po,  g_o);
    cudaGetSymbolAddress((void**)&pao, g_ao);
    cudaGetSymbolAddress((void**)&pws, g_wsum);

    cudaFuncSetAttribute(k_attn, cudaFuncAttributeMaxDynamicSharedMemorySize, 2*BB*KK*CC*4);

    const int nt64 = (N + 63) / 64;
    k_init<<<(BB*GG*GG*GG)/256, 256>>>(bw);
    k_scatter<<<(N + 255)/256, 256>>>(coords, N);
    k_conv<<<nt64, 256>>>(feats, conv_w, coords, N);
    k_bnstats<<<(N + 255)/256, 128>>>(N);
    k_bnapply<<<1024, 256>>>(gamma, beta, N);
    k_bk<<<BB*KK, 256>>>(probs, coords, N);
    k_ctx<<<dim3((N + 511)/512, BB), 256>>>(probs, coords, N);
    k_khv<<<BB*KK, 256>>>(ipw, ipb);
    k_gemm<true><<<nt64, 256>>>(px, ipw, ipb, pq, N, 0.25f);       // q = (x@Wq.T+bq)/sqrt(dh)
    k_attn<<<nt64, 512, 2*BB*KK*CC*4>>>(coords, N);
    k_gemm<true><<<nt64, 256>>>(po, opw, opb, pao, N, 1.0f);       // attn_out
    k_gemm<false><<<nt64, 256>>>(pao, pws, nullptr, y, N, 1.0f);   // y
}